// round 8
// baseline (speedup 1.0000x reference)
#include <cuda_runtime.h>
#include <cuda_fp16.h>
#include <math.h>
#include <stdint.h>

// ---------------- problem constants ----------------
#define B_   8
#define E_   8
#define C_   128
#define KW_  512
#define Mtot 16384          // B*L
#define KKd  4096           // KW*E
#define NNd  256            // 2*C

// ---------------- GEMM tiling ----------------
#define MT     64           // CTA M tile
#define KC     32           // K chunk (fp16 elems)
#define NCHUNK (KKd / KC)   // 128
#define NTH    256          // 8 warps: 2(M) x 4(N), warp tile 32x64
#define NCTA   (Mtot / MT)  // 256
#define STAGES 4

// smem (bytes)
#define PITCH   80          // 40 fp16 per row -> conflict-free ldmatrix
#define A_STG   (64 * PITCH)             // 5120 per stage
#define B_STG   (256 * PITCH)            // 20480 per stage
#define SM_A    0
#define SM_B    (STAGES * A_STG)         // 20480
#define SMEMSZ  (SM_B + STAGES * B_STG)  // 102400
// epilogue v2 tile overlay: [64][132] floats = 33792 B (fits in pipe region)
#define VPITCH  132

// fp16 weights, [n][kk] K-major; n<128 -> W1, n>=128 -> W2
__device__ __half g_Bh[(size_t)NNd * KKd];

// ---------------- helpers ----------------
__device__ __forceinline__ uint32_t smem_u32(const void* p) {
    uint32_t a;
    asm("{ .reg .u64 t; cvta.to.shared.u64 t, %1; cvt.u32.u64 %0, t; }" : "=r"(a) : "l"(p));
    return a;
}
__device__ __forceinline__ uint32_t pack_h2(float x, float y) {
    __half2 t = __floats2half2_rn(x, y);
    return *reinterpret_cast<uint32_t*>(&t);
}
__device__ __forceinline__ void ldmx4(uint32_t* r, uint32_t addr) {
    asm volatile("ldmatrix.sync.aligned.m8n8.x4.shared.b16 {%0,%1,%2,%3}, [%4];"
                 : "=r"(r[0]), "=r"(r[1]), "=r"(r[2]), "=r"(r[3]) : "r"(addr));
}
__device__ __forceinline__ void mma16816(float* d, const uint32_t* a, uint32_t b0, uint32_t b1) {
    asm volatile("mma.sync.aligned.m16n8k16.row.col.f32.f16.f16.f32 "
                 "{%0,%1,%2,%3}, {%4,%5,%6,%7}, {%8,%9}, {%0,%1,%2,%3};"
                 : "+f"(d[0]), "+f"(d[1]), "+f"(d[2]), "+f"(d[3])
                 : "r"(a[0]), "r"(a[1]), "r"(a[2]), "r"(a[3]), "r"(b0), "r"(b1));
}
__device__ __forceinline__ void sts64(uint32_t a, uint32_t x, uint32_t y) {
    asm volatile("st.shared.v2.b32 [%0], {%1,%2};" :: "r"(a), "r"(x), "r"(y) : "memory");
}
__device__ __forceinline__ void stsf2(uint32_t a, float x, float y) {
    asm volatile("st.shared.v2.f32 [%0], {%1,%2};" :: "r"(a), "f"(x), "f"(y) : "memory");
}
__device__ __forceinline__ void cpasync16(uint32_t dst, const void* src) {
    asm volatile("cp.async.cg.shared.global [%0], [%1], 16;" :: "r"(dst), "l"(src) : "memory");
}
__device__ __forceinline__ void cp_commit() { asm volatile("cp.async.commit_group;" ::: "memory"); }
__device__ __forceinline__ void cp_wait2() { asm volatile("cp.async.wait_group 2;" ::: "memory"); }
__device__ __forceinline__ void cp_wait1() { asm volatile("cp.async.wait_group 1;" ::: "memory"); }
__device__ __forceinline__ void atomicMaxFloat(float* addr, float val) {
    if (val >= 0.0f) atomicMax((int*)addr, __float_as_int(val));
    else             atomicMin((unsigned int*)addr, __float_as_uint(val));
}

// ---------------- prep: weights -> fp16 [n][kk], coalesced; also init out ----------------
__global__ void prep_weights(const float* __restrict__ W1, const float* __restrict__ W2,
                             float* __restrict__ out) {
    int idx = blockIdx.x * blockDim.x + threadIdx.x;   // over C_*KW_ = 65536
    if (idx < B_ * C_) out[idx] = -INFINITY;
    if (idx >= C_ * KW_) return;
    int c = idx / KW_;
    int k = idx % KW_;
    uint32_t p1[4], p2[4];
#pragma unroll
    for (int e2 = 0; e2 < 4; e2++) {
        float a0 = W1[((size_t)c * E_ + 2 * e2) * KW_ + k];
        float a1 = W1[((size_t)c * E_ + 2 * e2 + 1) * KW_ + k];
        p1[e2] = pack_h2(a0, a1);
        float b0 = W2[((size_t)c * E_ + 2 * e2) * KW_ + k];
        float b1v = W2[((size_t)c * E_ + 2 * e2 + 1) * KW_ + k];
        p2[e2] = pack_h2(b0, b1v);
    }
    *(uint4*)&g_Bh[(size_t)c * KKd + k * E_]        = make_uint4(p1[0], p1[1], p1[2], p1[3]);
    *(uint4*)&g_Bh[(size_t)(C_ + c) * KKd + k * E_] = make_uint4(p2[0], p2[1], p2[2], p2[3]);
}

// ---------------- main fused GEMM + gate + max ----------------
__global__ __launch_bounds__(NTH, 2)
void gemm_gate_max(const float* __restrict__ Z,
                   const float* __restrict__ b1,
                   const float* __restrict__ b2,
                   float* __restrict__ out) {
    extern __shared__ char smem[];
    const uint32_t sb = smem_u32(smem);
    const int tid  = threadIdx.x;
    const int wid  = tid >> 5;
    const int lane = tid & 31;
    const int wm   = wid & 1;        // M group (0..1), 32 rows each
    const int wn   = wid >> 1;       // N group (0..3), 64 cols each
    const int m_base = blockIdx.x * MT;

    const uint32_t fragBase = (uint32_t)((lane % 16) * PITCH + (lane / 16) * 16);
    // frag base addresses (stage 0)
    const uint32_t aFrag = sb + SM_A + (uint32_t)(wm * 32 * PITCH) + fragBase;
    const uint32_t bFrag = sb + SM_B + (uint32_t)(wn * 64 * PITCH) + fragBase;

    // ---- A gmem/smem mapping: 2 float4 per thread per chunk ----
    const float* aSrc0 = Z + (size_t)(m_base + (tid >> 3)) * KKd + (tid & 7) * 4;
    const uint32_t aDst0 = (uint32_t)((tid >> 3) * PITCH + (tid & 7) * 8);
    // second A granule: row += 32
#define ASRC(q) (aSrc0 + (size_t)(q) * 32 * KKd)
#define ADST(q) (aDst0 + (uint32_t)(q) * 32 * PITCH)

    // ---- B cp.async mapping: 4 granules (16B) per thread ----
    const __half* bSrc0 = g_Bh + (size_t)(tid >> 2) * KKd + (tid & 3) * 8;
    const uint32_t bDst0 = (uint32_t)((tid >> 2) * PITCH + (tid & 3) * 16);
#define BSRC(q) (bSrc0 + (size_t)(q) * 64 * KKd)
#define BDST(q) (bDst0 + (uint32_t)(q) * 64 * PITCH)

    float acc[2][8][4];
#pragma unroll
    for (int mi = 0; mi < 2; mi++)
#pragma unroll
        for (int ni = 0; ni < 8; ni++)
#pragma unroll
            for (int q = 0; q < 4; q++) acc[mi][ni][q] = 0.0f;

    // ---- prologue: B stages 0..2 via cp.async (3 groups); A stages 0..2 direct ----
#pragma unroll
    for (int s = 0; s < 3; s++) {
#pragma unroll
        for (int q = 0; q < 4; q++)
            cpasync16(sb + SM_B + s * B_STG + BDST(q), BSRC(q) + s * KC);
        cp_commit();
#pragma unroll
        for (int q = 0; q < 2; q++) {
            float4 v = *(const float4*)(ASRC(q) + s * KC);
            sts64(sb + SM_A + s * A_STG + ADST(q), pack_h2(v.x, v.y), pack_h2(v.z, v.w));
        }
    }
    // A for stage 3, packed fp16 in regs
    uint32_t ph[4];
    {
#pragma unroll
        for (int q = 0; q < 2; q++) {
            float4 v = *(const float4*)(ASRC(q) + 3 * KC);
            ph[2 * q]     = pack_h2(v.x, v.y);
            ph[2 * q + 1] = pack_h2(v.z, v.w);
        }
    }

    cp_wait2();        // stage 0 B arrived
    __syncthreads();   // stage 0 A visible

    // fragment double buffers
    uint32_t af0[2][4], bf0[4][4], af1[2][4], bf1[4][4];

    // preload slice 0 (stage 0, ks 0)
#pragma unroll
    for (int mi = 0; mi < 2; mi++) ldmx4(af0[mi], aFrag + mi * (16 * PITCH));
#pragma unroll
    for (int n2 = 0; n2 < 4; n2++) ldmx4(bf0[n2], bFrag + n2 * (16 * PITCH));

    for (int j = 0; j < NCHUNK; ++j) {
        cp_wait1();        // stage j+1 B arrived (stage j already arrived earlier)
        __syncthreads();   // stage j+1 A visible; buffer (j+3)%4 free

        const int wst = j + 3;
        if (wst < NCHUNK) {
            const uint32_t wo = (uint32_t)(wst & 3);
#pragma unroll
            for (int q = 0; q < 4; q++)
                cpasync16(sb + SM_B + wo * B_STG + BDST(q), BSRC(q) + wst * KC);
            sts64(sb + SM_A + wo * A_STG + ADST(0), ph[0], ph[1]);
            sts64(sb + SM_A + wo * A_STG + ADST(1), ph[2], ph[3]);
        }
        cp_commit();
        if (j + 4 < NCHUNK) {
#pragma unroll
            for (int q = 0; q < 2; q++) {
                float4 v = *(const float4*)(ASRC(q) + (j + 4) * KC);
                ph[2 * q]     = pack_h2(v.x, v.y);
                ph[2 * q + 1] = pack_h2(v.z, v.w);
            }
        }

        const uint32_t stc = (uint32_t)(j & 3);
        const uint32_t stn = (uint32_t)(((j + 1 < NCHUNK) ? j + 1 : j) & 3);

        // ---- half 1: preload slice (j, ks=1) into buf1; compute slice (j, ks=0) from buf0 ----
#pragma unroll
        for (int mi = 0; mi < 2; mi++)
            ldmx4(af1[mi], aFrag + stc * A_STG + mi * (16 * PITCH) + 32);
#pragma unroll
        for (int n2 = 0; n2 < 4; n2++)
            ldmx4(bf1[n2], bFrag + stc * B_STG + n2 * (16 * PITCH) + 32);
#pragma unroll
        for (int mi = 0; mi < 2; mi++)
#pragma unroll
            for (int ni = 0; ni < 8; ni++)
                mma16816(acc[mi][ni], af0[mi], bf0[ni >> 1][(ni & 1)], bf0[ni >> 1][(ni & 1) + 2]);

        // ---- half 2: preload slice (j+1, ks=0) into buf0; compute slice (j, ks=1) from buf1 ----
#pragma unroll
        for (int mi = 0; mi < 2; mi++)
            ldmx4(af0[mi], aFrag + stn * A_STG + mi * (16 * PITCH));
#pragma unroll
        for (int n2 = 0; n2 < 4; n2++)
            ldmx4(bf0[n2], bFrag + stn * B_STG + n2 * (16 * PITCH));
#pragma unroll
        for (int mi = 0; mi < 2; mi++)
#pragma unroll
            for (int ni = 0; ni < 8; ni++)
                mma16816(acc[mi][ni], af1[mi], bf1[ni >> 1][(ni & 1)], bf1[ni >> 1][(ni & 1) + 2]);
    }

    // ---- epilogue ----
    __syncthreads();   // pipe done; reuse smem as v2 tile [64][VPITCH] floats

    const int laneR = lane >> 2;
    const int laneC = (lane & 3) * 2;

    if (wn >= 2) {
#pragma unroll
        for (int mi = 0; mi < 2; mi++) {
#pragma unroll
            for (int ni = 0; ni < 8; ni++) {
                int r = wm * 32 + mi * 16 + laneR;
                int c = (wn - 2) * 64 + ni * 8 + laneC;
                uint32_t a0 = sb + (uint32_t)(r * (VPITCH * 4) + c * 4);
                stsf2(a0,                    acc[mi][ni][0], acc[mi][ni][1]);
                stsf2(a0 + 8 * (VPITCH * 4), acc[mi][ni][2], acc[mi][ni][3]);
            }
        }
    }
    __syncthreads();

    if (wn < 2) {
        const float* sV = (const float*)smem;
        const int bidx = blockIdx.x >> 5;   // 32 CTAs per batch
        float gm[8][2];
#pragma unroll
        for (int ni = 0; ni < 8; ni++) {
            const int c = wn * 64 + ni * 8 + laneC;
            const float bb1a = __ldg(&b1[c]),     bb1b = __ldg(&b1[c + 1]);
            const float bb2a = __ldg(&b2[c]),     bb2b = __ldg(&b2[c + 1]);
            float m0 = -INFINITY, m1 = -INFINITY;
#pragma unroll
            for (int mi = 0; mi < 2; mi++) {
                int r0 = wm * 32 + mi * 16 + laneR;
                float v2a0 = sV[r0 * VPITCH + c]           + bb2a;
                float v2b0 = sV[r0 * VPITCH + c + 1]       + bb2b;
                float v2a1 = sV[(r0 + 8) * VPITCH + c]     + bb2a;
                float v2b1 = sV[(r0 + 8) * VPITCH + c + 1] + bb2b;
                float g0 = (acc[mi][ni][0] + bb1a) / (1.0f + __expf(-v2a0));
                float g1 = (acc[mi][ni][1] + bb1b) / (1.0f + __expf(-v2b0));
                float g2 = (acc[mi][ni][2] + bb1a) / (1.0f + __expf(-v2a1));
                float g3 = (acc[mi][ni][3] + bb1b) / (1.0f + __expf(-v2b1));
                m0 = fmaxf(m0, fmaxf(g0, g2));
                m1 = fmaxf(m1, fmaxf(g1, g3));
            }
            gm[ni][0] = m0;
            gm[ni][1] = m1;
        }
#pragma unroll
        for (int ni = 0; ni < 8; ni++) {
#pragma unroll
            for (int off = 4; off < 32; off <<= 1) {
                gm[ni][0] = fmaxf(gm[ni][0], __shfl_xor_sync(0xffffffffu, gm[ni][0], off));
                gm[ni][1] = fmaxf(gm[ni][1], __shfl_xor_sync(0xffffffffu, gm[ni][1], off));
            }
        }
        if (laneR == 0) {
#pragma unroll
            for (int ni = 0; ni < 8; ni++) {
                int c = wn * 64 + ni * 8 + laneC;
                atomicMaxFloat(&out[bidx * C_ + c],     gm[ni][0]);
                atomicMaxFloat(&out[bidx * C_ + c + 1], gm[ni][1]);
            }
        }
    }
}

extern "C" void kernel_launch(void* const* d_in, const int* in_sizes, int n_in,
                              void* d_out, int out_size) {
    const float* z  = (const float*)d_in[0];
    const float* W1 = (const float*)d_in[1];
    const float* b1 = (const float*)d_in[2];
    const float* W2 = (const float*)d_in[3];
    const float* b2 = (const float*)d_in[4];
    float* out = (float*)d_out;
    (void)in_sizes; (void)n_in; (void)out_size;

    cudaFuncSetAttribute(gemm_gate_max, cudaFuncAttributeMaxDynamicSharedMemorySize, SMEMSZ);

    prep_weights<<<(C_ * KW_ + 255) / 256, 256>>>(W1, W2, out);
    gemm_gate_max<<<NCTA, NTH, SMEMSZ>>>(z, b1, b2, out);
}

// round 9
// speedup vs baseline: 1.5121x; 1.5121x over previous
#include <cuda_runtime.h>
#include <cuda_fp16.h>
#include <math.h>
#include <stdint.h>

// ---------------- problem constants ----------------
#define B_   8
#define E_   8
#define C_   128
#define KW_  512
#define Mtot 16384          // B*L
#define KKd  4096           // KW*E
#define NNd  256            // 2*C

// ---------------- GEMM tiling ----------------
#define MT     64           // CTA M tile
#define KC     64           // K chunk (fp16 elems)
#define NCHUNK (KKd / KC)   // 64
#define NTH    256          // 8 warps: 2(M) x 4(N), warp tile 32x64
#define NCTA   (Mtot / MT)  // 256

// smem (bytes)
#define PITCH   144         // 64 fp16 data + 8 pad -> conflict-free 8-row ldmatrix groups
#define A_STG   (64 * PITCH)         // 9216 per stage
#define B_STG   (256 * PITCH)        // 36864 per stage
#define SM_A    0
#define SM_B    (2 * A_STG)          // 18432
#define SMEMSZ  (SM_B + 2 * B_STG)   // 92160
// epilogue v2 tile overlay: [64][132] floats = 33792 B (fits in pipe region)
#define VPITCH  132

// fp16 weights, [n][kk] K-major; n<128 -> W1, n>=128 -> W2
__device__ __half g_Bh[(size_t)NNd * KKd];

// ---------------- helpers ----------------
__device__ __forceinline__ uint32_t smem_u32(const void* p) {
    uint32_t a;
    asm("{ .reg .u64 t; cvta.to.shared.u64 t, %1; cvt.u32.u64 %0, t; }" : "=r"(a) : "l"(p));
    return a;
}
__device__ __forceinline__ uint32_t pack_h2(float x, float y) {
    __half2 t = __floats2half2_rn(x, y);
    return *reinterpret_cast<uint32_t*>(&t);
}
__device__ __forceinline__ void ldmx4(uint32_t* r, uint32_t addr) {
    asm volatile("ldmatrix.sync.aligned.m8n8.x4.shared.b16 {%0,%1,%2,%3}, [%4];"
                 : "=r"(r[0]), "=r"(r[1]), "=r"(r[2]), "=r"(r[3]) : "r"(addr));
}
__device__ __forceinline__ void mma16816(float* d, const uint32_t* a, uint32_t b0, uint32_t b1) {
    asm volatile("mma.sync.aligned.m16n8k16.row.col.f32.f16.f16.f32 "
                 "{%0,%1,%2,%3}, {%4,%5,%6,%7}, {%8,%9}, {%0,%1,%2,%3};"
                 : "+f"(d[0]), "+f"(d[1]), "+f"(d[2]), "+f"(d[3])
                 : "r"(a[0]), "r"(a[1]), "r"(a[2]), "r"(a[3]), "r"(b0), "r"(b1));
}
__device__ __forceinline__ void sts64(uint32_t a, uint32_t x, uint32_t y) {
    asm volatile("st.shared.v2.b32 [%0], {%1,%2};" :: "r"(a), "r"(x), "r"(y) : "memory");
}
__device__ __forceinline__ void stsf2(uint32_t a, float x, float y) {
    asm volatile("st.shared.v2.f32 [%0], {%1,%2};" :: "r"(a), "f"(x), "f"(y) : "memory");
}
__device__ __forceinline__ void cpasync16(uint32_t dst, const void* src) {
    asm volatile("cp.async.cg.shared.global [%0], [%1], 16;" :: "r"(dst), "l"(src) : "memory");
}
__device__ __forceinline__ void cp_commit() { asm volatile("cp.async.commit_group;" ::: "memory"); }
__device__ __forceinline__ void cp_wait1() { asm volatile("cp.async.wait_group 1;" ::: "memory"); }
__device__ __forceinline__ void cp_wait0() { asm volatile("cp.async.wait_group 0;" ::: "memory"); }
__device__ __forceinline__ void atomicMaxFloat(float* addr, float val) {
    if (val >= 0.0f) atomicMax((int*)addr, __float_as_int(val));
    else             atomicMin((unsigned int*)addr, __float_as_uint(val));
}

// ---------------- prep: weights -> fp16 [n][kk], coalesced; also init out ----------------
__global__ void prep_weights(const float* __restrict__ W1, const float* __restrict__ W2,
                             float* __restrict__ out) {
    int idx = blockIdx.x * blockDim.x + threadIdx.x;   // over C_*KW_ = 65536
    if (idx < B_ * C_) out[idx] = -INFINITY;
    if (idx >= C_ * KW_) return;
    int c = idx / KW_;
    int k = idx % KW_;
    uint32_t p1[4], p2[4];
#pragma unroll
    for (int e2 = 0; e2 < 4; e2++) {
        float a0 = W1[((size_t)c * E_ + 2 * e2) * KW_ + k];
        float a1 = W1[((size_t)c * E_ + 2 * e2 + 1) * KW_ + k];
        p1[e2] = pack_h2(a0, a1);
        float b0 = W2[((size_t)c * E_ + 2 * e2) * KW_ + k];
        float b1v = W2[((size_t)c * E_ + 2 * e2 + 1) * KW_ + k];
        p2[e2] = pack_h2(b0, b1v);
    }
    *(uint4*)&g_Bh[(size_t)c * KKd + k * E_]        = make_uint4(p1[0], p1[1], p1[2], p1[3]);
    *(uint4*)&g_Bh[(size_t)(C_ + c) * KKd + k * E_] = make_uint4(p2[0], p2[1], p2[2], p2[3]);
}

// ---------------- main fused GEMM + gate + max ----------------
__global__ __launch_bounds__(NTH, 2)
void gemm_gate_max(const float* __restrict__ Z,
                   const float* __restrict__ b1,
                   const float* __restrict__ b2,
                   float* __restrict__ out) {
    extern __shared__ char smem[];
    const uint32_t sb = smem_u32(smem);
    const int tid  = threadIdx.x;
    const int wid  = tid >> 5;
    const int lane = tid & 31;
    const int wm   = wid & 1;        // M group (0..1), 32 rows each
    const int wn   = wid >> 1;       // N group (0..3), 64 cols each
    const int m_base = blockIdx.x * MT;

    const uint32_t fragBase = (uint32_t)((lane % 16) * PITCH + (lane / 16) * 16);
    const uint32_t wmOff = (uint32_t)(wm * 32 * PITCH);
    const uint32_t wnOff = (uint32_t)(wn * 64 * PITCH);

    // ---- A gmem/smem mapping: 4 float4 per thread per chunk (64 rows x 16 float4) ----
    const float* aSrc[4];
    uint32_t     aDst[4];
#pragma unroll
    for (int q = 0; q < 4; q++) {
        int i   = tid + q * 256;       // 0..1023
        int row = i >> 4;              // 0..63
        int f4  = i & 15;              // float4 index within row
        aSrc[q] = Z + (size_t)(m_base + row) * KKd + f4 * 4;
        aDst[q] = (uint32_t)(row * PITCH + f4 * 8);
    }
    // ---- B cp.async mapping: 8 granules (16B) per thread ----
    const __half* bSrc[8];
    uint32_t bDst[8];
#pragma unroll
    for (int q = 0; q < 8; q++) {
        int g  = tid + q * 256;        // 0..2047
        int n  = g >> 3;               // 0..255
        int ko = (g & 7) * 8;          // fp16 offset in row (0..56)
        bSrc[q] = g_Bh + (size_t)n * KKd + ko;
        bDst[q] = (uint32_t)(n * PITCH + ko * 2);
    }

    float acc[2][8][4];
#pragma unroll
    for (int mi = 0; mi < 2; mi++)
#pragma unroll
        for (int ni = 0; ni < 8; ni++)
#pragma unroll
            for (int q = 0; q < 4; q++) acc[mi][ni][q] = 0.0f;

    float4 pA[4];

    // ---- prologue: chunk 0 ----
#pragma unroll
    for (int q = 0; q < 4; q++) pA[q] = *(const float4*)(aSrc[q]);
#pragma unroll
    for (int q = 0; q < 8; q++)
        cpasync16(sb + SM_B + bDst[q], bSrc[q]);
    cp_commit();
#pragma unroll
    for (int q = 0; q < 4; q++) {
        float4 v = pA[q];
        sts64(sb + SM_A + aDst[q], pack_h2(v.x, v.y), pack_h2(v.z, v.w));
    }
#pragma unroll
    for (int q = 0; q < 4; q++) pA[q] = *(const float4*)(aSrc[q] + KC);

    for (int j = 0; j < NCHUNK; ++j) {
        const uint32_t cur = j & 1;
        const uint32_t nxt = cur ^ 1;

        __syncthreads();   // chunk j-1 consumed -> safe to overwrite stage nxt

        if (j + 1 < NCHUNK) {
            const int ke = (j + 1) * KC;
#pragma unroll
            for (int q = 0; q < 8; q++)
                cpasync16(sb + SM_B + nxt * B_STG + bDst[q], bSrc[q] + ke);
            cp_commit();
#pragma unroll
            for (int q = 0; q < 4; q++) {
                float4 v = pA[q];
                sts64(sb + SM_A + nxt * A_STG + aDst[q], pack_h2(v.x, v.y), pack_h2(v.z, v.w));
            }
            cp_wait1();
        } else {
            cp_wait0();
        }
        __syncthreads();   // stage cur fully visible

        if (j + 2 < NCHUNK) {
#pragma unroll
            for (int q = 0; q < 4; q++) pA[q] = *(const float4*)(aSrc[q] + (j + 2) * KC);
        }

        // ---- compute chunk j: 4 k16 slices, single fp16 pass ----
        const uint32_t sA = sb + SM_A + cur * A_STG;
        const uint32_t sB = sb + SM_B + cur * B_STG;

#pragma unroll
        for (int ks = 0; ks < 4; ks++) {
            const uint32_t ko = ks * 32;
            uint32_t af[2][4], bf[4][4];
#pragma unroll
            for (int mi = 0; mi < 2; mi++)
                ldmx4(af[mi], sA + wmOff + mi * (16 * PITCH) + ko + fragBase);
#pragma unroll
            for (int n2 = 0; n2 < 4; n2++)
                ldmx4(bf[n2], sB + wnOff + n2 * (16 * PITCH) + ko + fragBase);
#pragma unroll
            for (int mi = 0; mi < 2; mi++)
#pragma unroll
                for (int ni = 0; ni < 8; ni++)
                    mma16816(acc[mi][ni], af[mi], bf[ni >> 1][(ni & 1)], bf[ni >> 1][(ni & 1) + 2]);
        }
    }

    // ---- epilogue ----
    __syncthreads();   // pipe done; reuse smem as v2 tile [64][VPITCH] floats

    const int laneR = lane >> 2;
    const int laneC = (lane & 3) * 2;

    if (wn >= 2) {
#pragma unroll
        for (int mi = 0; mi < 2; mi++) {
#pragma unroll
            for (int ni = 0; ni < 8; ni++) {
                int r = wm * 32 + mi * 16 + laneR;
                int c = (wn - 2) * 64 + ni * 8 + laneC;
                uint32_t a0 = sb + (uint32_t)(r * (VPITCH * 4) + c * 4);
                stsf2(a0,                    acc[mi][ni][0], acc[mi][ni][1]);
                stsf2(a0 + 8 * (VPITCH * 4), acc[mi][ni][2], acc[mi][ni][3]);
            }
        }
    }
    __syncthreads();

    if (wn < 2) {
        const float* sV = (const float*)smem;
        const int bidx = blockIdx.x >> 5;   // 32 CTAs per batch
        float gm[8][2];
#pragma unroll
        for (int ni = 0; ni < 8; ni++) {
            const int c = wn * 64 + ni * 8 + laneC;
            const float bb1a = __ldg(&b1[c]),     bb1b = __ldg(&b1[c + 1]);
            const float bb2a = __ldg(&b2[c]),     bb2b = __ldg(&b2[c + 1]);
            float m0 = -INFINITY, m1 = -INFINITY;
#pragma unroll
            for (int mi = 0; mi < 2; mi++) {
                int r0 = wm * 32 + mi * 16 + laneR;
                float v2a0 = sV[r0 * VPITCH + c]           + bb2a;
                float v2b0 = sV[r0 * VPITCH + c + 1]       + bb2b;
                float v2a1 = sV[(r0 + 8) * VPITCH + c]     + bb2a;
                float v2b1 = sV[(r0 + 8) * VPITCH + c + 1] + bb2b;
                float g0 = (acc[mi][ni][0] + bb1a) / (1.0f + __expf(-v2a0));
                float g1 = (acc[mi][ni][1] + bb1b) / (1.0f + __expf(-v2b0));
                float g2 = (acc[mi][ni][2] + bb1a) / (1.0f + __expf(-v2a1));
                float g3 = (acc[mi][ni][3] + bb1b) / (1.0f + __expf(-v2b1));
                m0 = fmaxf(m0, fmaxf(g0, g2));
                m1 = fmaxf(m1, fmaxf(g1, g3));
            }
            gm[ni][0] = m0;
            gm[ni][1] = m1;
        }
#pragma unroll
        for (int ni = 0; ni < 8; ni++) {
#pragma unroll
            for (int off = 4; off < 32; off <<= 1) {
                gm[ni][0] = fmaxf(gm[ni][0], __shfl_xor_sync(0xffffffffu, gm[ni][0], off));
                gm[ni][1] = fmaxf(gm[ni][1], __shfl_xor_sync(0xffffffffu, gm[ni][1], off));
            }
        }
        if (laneR == 0) {
#pragma unroll
            for (int ni = 0; ni < 8; ni++) {
                int c = wn * 64 + ni * 8 + laneC;
                atomicMaxFloat(&out[bidx * C_ + c],     gm[ni][0]);
                atomicMaxFloat(&out[bidx * C_ + c + 1], gm[ni][1]);
            }
        }
    }
}

extern "C" void kernel_launch(void* const* d_in, const int* in_sizes, int n_in,
                              void* d_out, int out_size) {
    const float* z  = (const float*)d_in[0];
    const float* W1 = (const float*)d_in[1];
    const float* b1 = (const float*)d_in[2];
    const float* W2 = (const float*)d_in[3];
    const float* b2 = (const float*)d_in[4];
    float* out = (float*)d_out;
    (void)in_sizes; (void)n_in; (void)out_size;

    cudaFuncSetAttribute(gemm_gate_max, cudaFuncAttributeMaxDynamicSharedMemorySize, SMEMSZ);

    prep_weights<<<(C_ * KW_ + 255) / 256, 256>>>(W1, W2, out);
    gemm_gate_max<<<NCTA, NTH, SMEMSZ>>>(z, b1, b2, out);
}